// round 15
// baseline (speedup 1.0000x reference)
#include <cuda_runtime.h>
#include <cuda_fp16.h>
#include <cstdint>

#define NUM_GRAPHS 2048
#define DIM 256
#define HN 32
#define HG 64

typedef unsigned int u32;
typedef unsigned long long u64;

// ---- smem layout (bytes) ----
#define SM_WH 0u          // W^T fp16 [32 n][264 k] pad8, k-permuted  (16896)
// [0, 65536) is overlaid by Wg in the graph epilogue; gsw must be above.
#define SM_GSW 65536u     // per-warp graph sums 8 x 256 f32          (8192)
#define SMEM_BYTES 73728
#define WROW 528          // bytes per W^T row

__device__ __forceinline__ u32 smem_u32(const void* p) {
    u32 a;
    asm("{ .reg .u64 t; cvta.to.shared.u64 t, %1; cvt.u32.u64 %0, t; }" : "=r"(a) : "l"(p));
    return a;
}
__device__ __forceinline__ void ldsm4(u32& r0, u32& r1, u32& r2, u32& r3, u32 a) {
    asm volatile("ldmatrix.sync.aligned.m8n8.x4.shared.b16 {%0,%1,%2,%3}, [%4];"
        : "=r"(r0), "=r"(r1), "=r"(r2), "=r"(r3) : "r"(a));
}
__device__ __forceinline__ void mma16816(float* d, u32 a0, u32 a1, u32 a2, u32 a3,
                                         u32 b0, u32 b1) {
    asm volatile("mma.sync.aligned.m16n8k16.row.col.f32.f16.f16.f32 "
        "{%0,%1,%2,%3}, {%4,%5,%6,%7}, {%8,%9}, {%0,%1,%2,%3};"
        : "+f"(d[0]), "+f"(d[1]), "+f"(d[2]), "+f"(d[3])
        : "r"(a0), "r"(a1), "r"(a2), "r"(a3), "r"(b0), "r"(b1));
}
__device__ __forceinline__ u32 cvt2(float x0, float x1) {
    __half2 h = __float22half2_rn(make_float2(x0, x1));
    u32 r; __builtin_memcpy(&r, &h, 4); return r;
}
__device__ __forceinline__ void add2(u64& d, u64 a) {
    asm("add.rn.f32x2 %0, %0, %1;" : "+l"(d) : "l"(a));
}

// ---------------------------------------------------------------------------
// Fused kernel: CTA = 256 nodes = 4 graphs. grid 512, 256 threads, 2 CTAs/SM.
// A fragments loaded DIRECTLY from global via LDG.128 using a k-permutation
// (thread c holds k=4c..4c+3 within each k16 block); W is staged in smem with
// the SAME k-permutation so the standard B-ldsm matches. No X smem, no
// STS/ldsm-A, no main-loop barriers of any kind. fp16 single-term mma.sync.
// ---------------------------------------------------------------------------
__global__ __launch_bounds__(256, 2) void k_fused(
    const float* __restrict__ X, const float* __restrict__ Wn,
    const float* __restrict__ Wg, const float* __restrict__ bg,
    float* __restrict__ graph_out, float* __restrict__ node_out)
{
    extern __shared__ char smem[];
    const u32 sbase = smem_u32(smem);
    float* gsw = (float*)(smem + SM_GSW);

    const int t = threadIdx.x;
    const int w = t >> 5;
    const int lane = t & 31;
    const long tileRow = (long)blockIdx.x * 256;

    // ---- stage W^T : Wn[256][32] f32 -> [n][264k] fp16, k-permuted ----
    // Within k16 block: physical k -> unit=(k&2)>>1, halfpos=((k>>2)<<1)|(k&1)
    // so ldsm thread c's bh0 = k{4c,4c+1}, bh1 = k{4c+2,4c+3}.
    {
        const float4* W4 = (const float4*)Wn;
#pragma unroll
        for (int i = 0; i < 8; i++) {
            int idx = t + 256 * i;       // 2048 float4
            float4 v4 = W4[idx];
            int d = idx >> 3;            // k dim 0..255
            int n0 = (idx & 7) * 4;
            int kk = d & 15;
            u32 koff = (u32)(d >> 4) * 32u + (u32)((kk & 2) >> 1) * 16u
                     + (u32)(((kk >> 2) << 1) | (kk & 1)) * 2u;
            float vv[4] = {v4.x, v4.y, v4.z, v4.w};
#pragma unroll
            for (int j = 0; j < 4; j++)
                *(__half*)(smem + SM_WH + (u32)(n0 + j) * WROW + koff) =
                    __float2half_rn(vv[j]);
        }
    }
    __syncthreads();   // W visible; no more barriers until epilogue

    // ---- geometry ----
    const int aq = lane >> 3;
    const int ai = lane & 7;
    const u32 bbase = (u32)(aq * 8 + ai) * WROW;
    // A loads: row r = w*32 + (lane>>2) (+8/+16/+24), float4 col = 4s + (lane&3)
    const float4* xq = (const float4*)X + (tileRow + w * 32 + (lane >> 2)) * 64 + (lane & 3);

    float acc[2][4][4];
#pragma unroll
    for (int mt = 0; mt < 2; mt++)
#pragma unroll
        for (int nt = 0; nt < 4; nt++)
#pragma unroll
            for (int e = 0; e < 4; e++) acc[mt][nt][e] = 0.f;

    // prologue: step 0 loads (rows r, r+8, r+16, r+24)
    float4 v0 = xq[0], v1 = xq[512], v2 = xq[1024], v3 = xq[1536];

#pragma unroll
    for (int s = 0; s < 16; s++) {
        // ---- prefetch step s+1 ----
        float4 n0_, n1_, n2_, n3_;
        if (s < 15) {
            int o = (s + 1) * 4;
            n0_ = xq[o]; n1_ = xq[o + 512]; n2_ = xq[o + 1024]; n3_ = xq[o + 1536];
        }

        // ---- convert to A fragments (k-permuted packing) ----
        u32 A0 = cvt2(v0.x, v0.y), A2 = cvt2(v0.z, v0.w);   // row r   (mt0)
        u32 A1 = cvt2(v1.x, v1.y), A3 = cvt2(v1.z, v1.w);   // row r+8
        u32 A4 = cvt2(v2.x, v2.y), A6 = cvt2(v2.z, v2.w);   // row r+16 (mt1)
        u32 A5 = cvt2(v3.x, v3.y), A7 = cvt2(v3.z, v3.w);   // row r+24

        // ---- graph partials: sum thread's 4 rows (packed adds) ----
        u64 pxy, pzw;
        {
            u64 a, b, c, d;
            __builtin_memcpy(&a, &v0.x, 8); __builtin_memcpy(&b, &v1.x, 8);
            __builtin_memcpy(&c, &v2.x, 8); __builtin_memcpy(&d, &v3.x, 8);
            pxy = a; add2(pxy, b); add2(pxy, c); add2(pxy, d);
            __builtin_memcpy(&a, &v0.z, 8); __builtin_memcpy(&b, &v1.z, 8);
            __builtin_memcpy(&c, &v2.z, 8); __builtin_memcpy(&d, &v3.z, 8);
            pzw = a; add2(pzw, b); add2(pzw, c); add2(pzw, d);
        }

        // ---- B fragments + MMA ----
        const u32 bko = (u32)s * 32u;
        u32 bh0[4], bh1[4];
        ldsm4(bh0[0], bh0[1], bh0[2], bh0[3], sbase + SM_WH + bbase + bko);
        ldsm4(bh1[0], bh1[1], bh1[2], bh1[3], sbase + SM_WH + bbase + bko + 16);

#pragma unroll
        for (int nt = 0; nt < 4; nt++)
            mma16816(acc[0][nt], A0, A1, A2, A3, bh0[nt], bh1[nt]);
#pragma unroll
        for (int nt = 0; nt < 4; nt++)
            mma16816(acc[1][nt], A4, A5, A6, A7, bh0[nt], bh1[nt]);

        // ---- reduce partials across the 8 row-lanes (xor 4,8,16) ----
        {
            float4 p;
            __builtin_memcpy(&p.x, &pxy, 8);
            __builtin_memcpy(&p.z, &pzw, 8);
#pragma unroll
            for (int m = 4; m <= 16; m <<= 1) {
                p.x += __shfl_xor_sync(0xffffffffu, p.x, m);
                p.y += __shfl_xor_sync(0xffffffffu, p.y, m);
                p.z += __shfl_xor_sync(0xffffffffu, p.z, m);
                p.w += __shfl_xor_sync(0xffffffffu, p.w, m);
            }
            if (lane < 4)   // lane==c: cols s*16 + 4c .. +3, distinct per step
                *(float4*)&gsw[w * 256 + s * 16 + lane * 4] = p;
        }

        v0 = n0_; v1 = n1_; v2 = n2_; v3 = n3_;
    }

    // ---- node_out epilogue ----
    {
        const int rr = lane >> 2;
        const int cc = (lane & 3) * 2;
#pragma unroll
        for (int mt = 0; mt < 2; mt++) {
            long r = tileRow + w * 32 + mt * 16 + rr;
#pragma unroll
            for (int nt = 0; nt < 4; nt++) {
                float* dd = acc[mt][nt];
                int c0 = nt * 8 + cc;
                *(float2*)(node_out + r * HN + c0) = make_float2(dd[0], dd[1]);
                *(float2*)(node_out + (r + 8) * HN + c0) = make_float2(dd[2], dd[3]);
            }
        }
    }

    // ---- graph head: stage Wg (64 KB) over smem[0..65536), then dot ----
    __syncthreads();
    {
        const float4* Wg4 = (const float4*)Wg;
        float4* Wd = (float4*)smem;
#pragma unroll
        for (int i = 0; i < 16; i++) Wd[t + 256 * i] = Wg4[t + 256 * i];
    }
    __syncthreads();
    {
        const float* Wgs = (const float*)smem;     // [256 d][64 j]
        const int gg = t >> 6;                     // graph in CTA 0..3
        const int j = t & 63;
        const float* g0 = gsw + (2 * gg) * 256;    // two warps per graph
        const float* g1 = gsw + (2 * gg + 1) * 256;
        float s = 0.f;
#pragma unroll 8
        for (int d = 0; d < 256; d++)
            s += (g0[d] + g1[d]) * Wgs[d * 64 + j];
        graph_out[(blockIdx.x * 4 + gg) * HG + j] = s * (1.0f / 64.0f) + __ldg(bg + j);
    }
}

// ---------------------------------------------------------------------------
extern "C" void kernel_launch(void* const* d_in, const int* in_sizes, int n_in,
                              void* d_out, int out_size) {
    const float* X  = (const float*)d_in[0];
    // d_in[1] = batch (int32): 64 consecutive nodes per graph, implicit
    const float* Wg = (const float*)d_in[2];
    const float* bg = (const float*)d_in[3];
    const float* Wn = (const float*)d_in[4];
    float* out = (float*)d_out;
    (void)in_sizes; (void)n_in; (void)out_size;

    cudaFuncSetAttribute(k_fused, cudaFuncAttributeMaxDynamicSharedMemorySize, SMEM_BYTES);

    // output layout: graph_out [2048*64] first, then node_out [131072*32]
    k_fused<<<512, 256, SMEM_BYTES>>>(X, Wn, Wg, bg, out, out + NUM_GRAPHS * HG);
}

// round 16
// speedup vs baseline: 1.0104x; 1.0104x over previous
#include <cuda_runtime.h>
#include <cuda_fp16.h>
#include <cstdint>

#define NUM_GRAPHS 2048
#define DIM 256
#define HN 32
#define HG 64

typedef unsigned int u32;
typedef unsigned long long u64;

// ---- smem layout (bytes) ----
#define SM_RING 0u        // per-warp 3-stage ring: w*6144 + st*2048  (49152)
#define SM_WH  49152u     // W^T fp16 [32 n][264 k] pad8, k-permuted  (16896)
// graph epilogue overlays smem[0..65536) with Wg; ring+W are dead there.
#define SM_GSW 66048u     // per-warp graph sums 8 x 256 f32          (8192)
#define SMEM_BYTES 74240
#define WROW 528          // bytes per W^T row

__device__ __forceinline__ u32 smem_u32(const void* p) {
    u32 a;
    asm("{ .reg .u64 t; cvta.to.shared.u64 t, %1; cvt.u32.u64 %0, t; }" : "=r"(a) : "l"(p));
    return a;
}
__device__ __forceinline__ void ldsm4(u32& r0, u32& r1, u32& r2, u32& r3, u32 a) {
    asm volatile("ldmatrix.sync.aligned.m8n8.x4.shared.b16 {%0,%1,%2,%3}, [%4];"
        : "=r"(r0), "=r"(r1), "=r"(r2), "=r"(r3) : "r"(a));
}
__device__ __forceinline__ void mma16816(float* d, u32 a0, u32 a1, u32 a2, u32 a3,
                                         u32 b0, u32 b1) {
    asm volatile("mma.sync.aligned.m16n8k16.row.col.f32.f16.f16.f32 "
        "{%0,%1,%2,%3}, {%4,%5,%6,%7}, {%8,%9}, {%0,%1,%2,%3};"
        : "+f"(d[0]), "+f"(d[1]), "+f"(d[2]), "+f"(d[3])
        : "r"(a0), "r"(a1), "r"(a2), "r"(a3), "r"(b0), "r"(b1));
}
__device__ __forceinline__ u32 cvt2(float x0, float x1) {
    __half2 h = __float22half2_rn(make_float2(x0, x1));
    u32 r; __builtin_memcpy(&r, &h, 4); return r;
}
__device__ __forceinline__ void add2(u64& d, u64 a) {
    asm("add.rn.f32x2 %0, %0, %1;" : "+l"(d) : "l"(a));
}
__device__ __forceinline__ void cp16(u32 dst, const float* src) {
    asm volatile("cp.async.cg.shared.global [%0], [%1], 16;"
        :: "r"(dst), "l"(src) : "memory");
}
__device__ __forceinline__ void cp_commit() {
    asm volatile("cp.async.commit_group;" ::: "memory");
}
__device__ __forceinline__ void cp_wait2() {
    asm volatile("cp.async.wait_group 2;" ::: "memory");
}

// ---------------------------------------------------------------------------
// Fused kernel: CTA = 256 nodes = 4 graphs. grid 512, 256 threads, 2 CTAs/SM.
// X streamed via cp.async into a warp-private 3-stage fp32 ring; each thread
// copies EXACTLY the granules it consumes (self-dependency only) -> the main
// loop has no barriers of any kind, just cp.async.wait_group.
// A fragments built in registers with a k-permutation; W staged in smem with
// the same permutation so the standard B-ldsm matches. fp16 mma, fp32 accum.
// ---------------------------------------------------------------------------
__global__ __launch_bounds__(256, 2) void k_fused(
    const float* __restrict__ X, const float* __restrict__ Wn,
    const float* __restrict__ Wg, const float* __restrict__ bg,
    float* __restrict__ graph_out, float* __restrict__ node_out)
{
    extern __shared__ char smem[];
    const u32 sbase = smem_u32(smem);
    float* gsw = (float*)(smem + SM_GSW);

    const int t = threadIdx.x;
    const int w = t >> 5;
    const int lane = t & 31;
    const long tileRow = (long)blockIdx.x * 256;

    // ---- geometry ----
    const int rg = lane >> 2;          // row-in-group 0..7
    const int c  = lane & 3;           // k-granule / fragment col pair
    // thread's global source: row tileRow + w*32 + rg (+8j), floats col s*16 + c*4
    const float* xg = X + (tileRow + w * 32 + rg) * 256 + c * 4;
    const u32 ring = sbase + SM_RING + (u32)w * 6144u;
    const u32 my_off = (u32)rg * 64u + (u32)c * 16u;   // within a 2KB stage
    const u32 ring_off = SM_RING + (u32)w * 6144u + my_off; // for LDS pointer

    // ---- prologue: cp.async stages 0..2 (each its own commit group) ----
#pragma unroll
    for (int st = 0; st < 3; st++) {
        u32 dst = ring + (u32)st * 2048u + my_off;
#pragma unroll
        for (int j = 0; j < 4; j++)
            cp16(dst + (u32)j * 512u, xg + st * 16 + j * 2048);
        cp_commit();
    }

    // ---- stage W^T : Wn[256][32] f32 -> [n][264k] fp16, k-permuted ----
    // Within k16 block: k -> unit=(k&2)>>1, halfpos=((k>>2)<<1)|(k&1)
    // so ldsm thread c's bh0 = k{4c,4c+1}, bh1 = k{4c+2,4c+3}.
    {
        const float4* W4 = (const float4*)Wn;
#pragma unroll
        for (int i = 0; i < 8; i++) {
            int idx = t + 256 * i;       // 2048 float4
            float4 v4 = W4[idx];
            int d = idx >> 3;            // k dim 0..255
            int n0 = (idx & 7) * 4;
            int kk = d & 15;
            u32 koff = (u32)(d >> 4) * 32u + (u32)((kk & 2) >> 1) * 16u
                     + (u32)(((kk >> 2) << 1) | (kk & 1)) * 2u;
            float vv[4] = {v4.x, v4.y, v4.z, v4.w};
#pragma unroll
            for (int j = 0; j < 4; j++)
                *(__half*)(smem + SM_WH + (u32)(n0 + j) * WROW + koff) =
                    __float2half_rn(vv[j]);
        }
    }
    __syncthreads();   // W visible; no more barriers until epilogue

    const int aq = lane >> 3;
    const int ai = lane & 7;
    const u32 bbase = (u32)(aq * 8 + ai) * WROW;

    float acc[2][4][4];
#pragma unroll
    for (int mt = 0; mt < 2; mt++)
#pragma unroll
        for (int nt = 0; nt < 4; nt++)
#pragma unroll
            for (int e = 0; e < 4; e++) acc[mt][nt][e] = 0.f;

#pragma unroll
    for (int s = 0; s < 16; s++) {
        // ---- stage s ready (this thread's own copies) ----
        cp_wait2();
        const char* stg = smem + ring_off + (u32)(s % 3) * 2048u;
        float4 v0 = *(const float4*)(stg);          // row rg
        float4 v1 = *(const float4*)(stg + 512);    // row rg+8
        float4 v2 = *(const float4*)(stg + 1024);   // row rg+16
        float4 v3 = *(const float4*)(stg + 1536);   // row rg+24

        // ---- refill this slot with stage s+3 (write lands >>29cyc later) ----
        if (s < 13) {
            u32 dst = ring + (u32)(s % 3) * 2048u + my_off;
#pragma unroll
            for (int j = 0; j < 4; j++)
                cp16(dst + (u32)j * 512u, xg + (s + 3) * 16 + j * 2048);
        }
        cp_commit();   // always commit (empty groups keep wait counts aligned)

        // ---- convert to A fragments (k-permuted packing) ----
        u32 A0 = cvt2(v0.x, v0.y), A2 = cvt2(v0.z, v0.w);   // row rg    (mt0)
        u32 A1 = cvt2(v1.x, v1.y), A3 = cvt2(v1.z, v1.w);   // row rg+8
        u32 A4 = cvt2(v2.x, v2.y), A6 = cvt2(v2.z, v2.w);   // row rg+16 (mt1)
        u32 A5 = cvt2(v3.x, v3.y), A7 = cvt2(v3.z, v3.w);   // row rg+24

        // ---- graph partials: sum thread's 4 rows (packed adds) ----
        u64 pxy, pzw;
        {
            u64 a, b, cc_, d;
            __builtin_memcpy(&a, &v0.x, 8); __builtin_memcpy(&b, &v1.x, 8);
            __builtin_memcpy(&cc_, &v2.x, 8); __builtin_memcpy(&d, &v3.x, 8);
            pxy = a; add2(pxy, b); add2(pxy, cc_); add2(pxy, d);
            __builtin_memcpy(&a, &v0.z, 8); __builtin_memcpy(&b, &v1.z, 8);
            __builtin_memcpy(&cc_, &v2.z, 8); __builtin_memcpy(&d, &v3.z, 8);
            pzw = a; add2(pzw, b); add2(pzw, cc_); add2(pzw, d);
        }

        // ---- B fragments + MMA ----
        const u32 bko = (u32)s * 32u;
        u32 bh0[4], bh1[4];
        ldsm4(bh0[0], bh0[1], bh0[2], bh0[3], sbase + SM_WH + bbase + bko);
        ldsm4(bh1[0], bh1[1], bh1[2], bh1[3], sbase + SM_WH + bbase + bko + 16);

#pragma unroll
        for (int nt = 0; nt < 4; nt++)
            mma16816(acc[0][nt], A0, A1, A2, A3, bh0[nt], bh1[nt]);
#pragma unroll
        for (int nt = 0; nt < 4; nt++)
            mma16816(acc[1][nt], A4, A5, A6, A7, bh0[nt], bh1[nt]);

        // ---- reduce partials across the 8 row-lanes (xor 4,8,16) ----
        {
            float4 p;
            __builtin_memcpy(&p.x, &pxy, 8);
            __builtin_memcpy(&p.z, &pzw, 8);
#pragma unroll
            for (int m = 4; m <= 16; m <<= 1) {
                p.x += __shfl_xor_sync(0xffffffffu, p.x, m);
                p.y += __shfl_xor_sync(0xffffffffu, p.y, m);
                p.z += __shfl_xor_sync(0xffffffffu, p.z, m);
                p.w += __shfl_xor_sync(0xffffffffu, p.w, m);
            }
            if (lane < 4)   // lane==c: cols s*16 + 4c..+3, distinct per step
                *(float4*)&gsw[w * 256 + s * 16 + lane * 4] = p;
        }
    }

    // ---- node_out epilogue ----
    {
        const int rr = lane >> 2;
        const int cc = (lane & 3) * 2;
#pragma unroll
        for (int mt = 0; mt < 2; mt++) {
            long r = tileRow + w * 32 + mt * 16 + rr;
#pragma unroll
            for (int nt = 0; nt < 4; nt++) {
                float* dd = acc[mt][nt];
                int c0 = nt * 8 + cc;
                *(float2*)(node_out + r * HN + c0) = make_float2(dd[0], dd[1]);
                *(float2*)(node_out + (r + 8) * HN + c0) = make_float2(dd[2], dd[3]);
            }
        }
    }

    // ---- graph head: stage Wg (64 KB) over smem[0..65536), then dot ----
    __syncthreads();
    {
        const float4* Wg4 = (const float4*)Wg;
        float4* Wd = (float4*)smem;
#pragma unroll
        for (int i = 0; i < 16; i++) Wd[t + 256 * i] = Wg4[t + 256 * i];
    }
    __syncthreads();
    {
        const float* Wgs = (const float*)smem;     // [256 d][64 j]
        const int gg = t >> 6;                     // graph in CTA 0..3
        const int j = t & 63;
        const float* g0 = gsw + (2 * gg) * 256;    // two warps per graph
        const float* g1 = gsw + (2 * gg + 1) * 256;
        float s = 0.f;
#pragma unroll 8
        for (int d = 0; d < 256; d++)
            s += (g0[d] + g1[d]) * Wgs[d * 64 + j];
        graph_out[(blockIdx.x * 4 + gg) * HG + j] = s * (1.0f / 64.0f) + __ldg(bg + j);
    }
}

// ---------------------------------------------------------------------------
extern "C" void kernel_launch(void* const* d_in, const int* in_sizes, int n_in,
                              void* d_out, int out_size) {
    const float* X  = (const float*)d_in[0];
    // d_in[1] = batch (int32): 64 consecutive nodes per graph, implicit
    const float* Wg = (const float*)d_in[2];
    const float* bg = (const float*)d_in[3];
    const float* Wn = (const float*)d_in[4];
    float* out = (float*)d_out;
    (void)in_sizes; (void)n_in; (void)out_size;

    cudaFuncSetAttribute(k_fused, cudaFuncAttributeMaxDynamicSharedMemorySize, SMEM_BYTES);

    // output layout: graph_out [2048*64] first, then node_out [131072*32]
    k_fused<<<512, 256, SMEM_BYTES>>>(X, Wn, Wg, bg, out, out + NUM_GRAPHS * HG);
}

// round 17
// speedup vs baseline: 1.0350x; 1.0244x over previous
#include <cuda_runtime.h>
#include <cuda_fp16.h>
#include <cstdint>

#define NUM_GRAPHS 2048
#define HN 32
#define HG 64

typedef unsigned int u32;
typedef unsigned long long u64;

// ---- smem layout (bytes) ----
#define SM_WH 0u          // W^T fp16 [32 n][264 k] pad8, k-permuted  (16896)
// graph epilogue overlays smem[0..65536) with Wg; gsw must live above.
#define SM_GSW 65536u     // per-warp graph half-sums 8 x 2 x 256 f32 (16384)
#define SMEM_BYTES 81920
#define WROW 528          // bytes per W^T row

__device__ __forceinline__ u32 smem_u32(const void* p) {
    u32 a;
    asm("{ .reg .u64 t; cvta.to.shared.u64 t, %1; cvt.u32.u64 %0, t; }" : "=r"(a) : "l"(p));
    return a;
}
__device__ __forceinline__ void ldsm4(u32& r0, u32& r1, u32& r2, u32& r3, u32 a) {
    asm volatile("ldmatrix.sync.aligned.m8n8.x4.shared.b16 {%0,%1,%2,%3}, [%4];"
        : "=r"(r0), "=r"(r1), "=r"(r2), "=r"(r3) : "r"(a));
}
__device__ __forceinline__ void mma16816(float* d, u32 a0, u32 a1, u32 a2, u32 a3,
                                         u32 b0, u32 b1) {
    asm volatile("mma.sync.aligned.m16n8k16.row.col.f32.f16.f16.f32 "
        "{%0,%1,%2,%3}, {%4,%5,%6,%7}, {%8,%9}, {%0,%1,%2,%3};"
        : "+f"(d[0]), "+f"(d[1]), "+f"(d[2]), "+f"(d[3])
        : "r"(a0), "r"(a1), "r"(a2), "r"(a3), "r"(b0), "r"(b1));
}
__device__ __forceinline__ u32 cvt2(float x0, float x1) {
    __half2 h = __float22half2_rn(make_float2(x0, x1));
    u32 r; __builtin_memcpy(&r, &h, 4); return r;
}
__device__ __forceinline__ void add2(u64& d, u64 a) {
    asm("add.rn.f32x2 %0, %0, %1;" : "+l"(d) : "l"(a));
}

// ---------------------------------------------------------------------------
// Fused kernel: CTA = 256 nodes = 4 graphs. grid 512, 256 threads, 2 CTAs/SM.
// A fragments loaded DIRECTLY from global (k-permuted layout; W staged in smem
// with the same permutation so the standard B-ldsm matches). Register
// double-buffer gives prefetch depth 2 (~2 step times > DRAM latency).
// Graph partials: 2 shfl rounds only; two half-sums stored per warp.
// No main-loop barriers. fp16 single-term mma, fp32 accum.
// ---------------------------------------------------------------------------
__global__ __launch_bounds__(256, 2) void k_fused(
    const float* __restrict__ X, const float* __restrict__ Wn,
    const float* __restrict__ Wg, const float* __restrict__ bg,
    float* __restrict__ graph_out, float* __restrict__ node_out)
{
    extern __shared__ char smem[];
    const u32 sbase = smem_u32(smem);
    float* gsw = (float*)(smem + SM_GSW);

    const int t = threadIdx.x;
    const int w = t >> 5;
    const int lane = t & 31;
    const long tileRow = (long)blockIdx.x * 256;

    // ---- stage W^T : Wn[256][32] f32 -> [n][264k] fp16, k-permuted ----
    // Within k16 block: k -> unit=(k&2)>>1, halfpos=((k>>2)<<1)|(k&1)
    // so ldsm thread c's bh0 = k{4c,4c+1}, bh1 = k{4c+2,4c+3}.
    {
        const float4* W4 = (const float4*)Wn;
#pragma unroll
        for (int i = 0; i < 8; i++) {
            int idx = t + 256 * i;       // 2048 float4
            float4 v4 = W4[idx];
            int d = idx >> 3;            // k dim 0..255
            int n0 = (idx & 7) * 4;
            int kk = d & 15;
            u32 koff = (u32)(d >> 4) * 32u + (u32)((kk & 2) >> 1) * 16u
                     + (u32)(((kk >> 2) << 1) | (kk & 1)) * 2u;
            float vv[4] = {v4.x, v4.y, v4.z, v4.w};
#pragma unroll
            for (int j = 0; j < 4; j++)
                *(__half*)(smem + SM_WH + (u32)(n0 + j) * WROW + koff) =
                    __float2half_rn(vv[j]);
        }
    }
    __syncthreads();   // W visible; no more barriers until epilogue

    // ---- geometry ----
    const int aq = lane >> 3;
    const int ai = lane & 7;
    const u32 bbase = (u32)(aq * 8 + ai) * WROW;
    // A loads: row r = w*32 + (lane>>2) (+8/+16/+24), float4 col = 4s + (lane&3)
    const float4* xq = (const float4*)X + (tileRow + w * 32 + (lane >> 2)) * 64 + (lane & 3);

    float acc[2][4][4];
#pragma unroll
    for (int mt = 0; mt < 2; mt++)
#pragma unroll
        for (int nt = 0; nt < 4; nt++)
#pragma unroll
            for (int e = 0; e < 4; e++) acc[mt][nt][e] = 0.f;

    // ---- register double buffer: steps s and s+1 in flight ----
    float4 vb[2][4];
#pragma unroll
    for (int j = 0; j < 4; j++) vb[0][j] = xq[j * 512];
#pragma unroll
    for (int j = 0; j < 4; j++) vb[1][j] = xq[4 + j * 512];

#pragma unroll 2
    for (int s = 0; s < 16; s++) {
        const int sb = s & 1;
        float4 v0 = vb[sb][0], v1 = vb[sb][1], v2 = vb[sb][2], v3 = vb[sb][3];

        // ---- convert to A fragments (k-permuted packing) ----
        u32 A0 = cvt2(v0.x, v0.y), A2 = cvt2(v0.z, v0.w);   // row r     (mt0)
        u32 A1 = cvt2(v1.x, v1.y), A3 = cvt2(v1.z, v1.w);   // row r+8
        u32 A4 = cvt2(v2.x, v2.y), A6 = cvt2(v2.z, v2.w);   // row r+16  (mt1)
        u32 A5 = cvt2(v3.x, v3.y), A7 = cvt2(v3.z, v3.w);   // row r+24

        // ---- prefetch step s+2 into the freed buffer ----
        if (s < 14) {
            int o = (s + 2) * 4;
#pragma unroll
            for (int j = 0; j < 4; j++) vb[sb][j] = xq[o + j * 512];
        }

        // ---- graph partials: sum thread's 4 rows (packed adds) ----
        u64 pxy, pzw;
        {
            u64 a, b, cc_, d;
            __builtin_memcpy(&a, &v0.x, 8); __builtin_memcpy(&b, &v1.x, 8);
            __builtin_memcpy(&cc_, &v2.x, 8); __builtin_memcpy(&d, &v3.x, 8);
            pxy = a; add2(pxy, b); add2(pxy, cc_); add2(pxy, d);
            __builtin_memcpy(&a, &v0.z, 8); __builtin_memcpy(&b, &v1.z, 8);
            __builtin_memcpy(&cc_, &v2.z, 8); __builtin_memcpy(&d, &v3.z, 8);
            pzw = a; add2(pzw, b); add2(pzw, cc_); add2(pzw, d);
        }

        // ---- B fragments + MMA ----
        const u32 bko = (u32)s * 32u;
        u32 bh0[4], bh1[4];
        ldsm4(bh0[0], bh0[1], bh0[2], bh0[3], sbase + SM_WH + bbase + bko);
        ldsm4(bh1[0], bh1[1], bh1[2], bh1[3], sbase + SM_WH + bbase + bko + 16);

#pragma unroll
        for (int nt = 0; nt < 4; nt++)
            mma16816(acc[0][nt], A0, A1, A2, A3, bh0[nt], bh1[nt]);
#pragma unroll
        for (int nt = 0; nt < 4; nt++)
            mma16816(acc[1][nt], A4, A5, A6, A7, bh0[nt], bh1[nt]);

        // ---- reduce partials: 2 shfl rounds (xor 4, 8); two half-sums ----
        {
            float4 p;
            __builtin_memcpy(&p.x, &pxy, 8);
            __builtin_memcpy(&p.z, &pzw, 8);
#pragma unroll
            for (int m = 4; m <= 8; m <<= 1) {
                p.x += __shfl_xor_sync(0xffffffffu, p.x, m);
                p.y += __shfl_xor_sync(0xffffffffu, p.y, m);
                p.z += __shfl_xor_sync(0xffffffffu, p.z, m);
                p.w += __shfl_xor_sync(0xffffffffu, p.w, m);
            }
            if ((lane & 12) == 0) {   // lanes 0-3 (half 0), 16-19 (half 1)
                int half = lane >> 4;
                *(float4*)&gsw[w * 512 + half * 256 + s * 16 + (lane & 3) * 4] = p;
            }
        }
    }

    // ---- node_out epilogue ----
    {
        const int rr = lane >> 2;
        const int cc = (lane & 3) * 2;
#pragma unroll
        for (int mt = 0; mt < 2; mt++) {
            long r = tileRow + w * 32 + mt * 16 + rr;
#pragma unroll
            for (int nt = 0; nt < 4; nt++) {
                float* dd = acc[mt][nt];
                int c0 = nt * 8 + cc;
                *(float2*)(node_out + r * HN + c0) = make_float2(dd[0], dd[1]);
                *(float2*)(node_out + (r + 8) * HN + c0) = make_float2(dd[2], dd[3]);
            }
        }
    }

    // ---- graph head: combine half-sums; stage Wg over smem[0..65536) ----
    __syncthreads();   // all gsw writes visible
    {
        // combine 4 partial arrays per graph into gsw[g*1024 + d]
#pragma unroll
        for (int i = t; i < 1024; i += 256) {
            int g = i >> 8, d = i & 255;
            float* b_ = gsw + g * 1024 + d;
            float a = b_[0] + b_[256] + b_[512] + b_[768];
            b_[0] = a;
        }
        const float4* Wg4 = (const float4*)Wg;
        float4* Wd = (float4*)smem;
#pragma unroll
        for (int i = 0; i < 16; i++) Wd[t + 256 * i] = Wg4[t + 256 * i];
    }
    __syncthreads();
    {
        const float* Wgs = (const float*)smem;     // [256 d][64 j]
        const int gg = t >> 6;                     // graph in CTA 0..3
        const int j = t & 63;
        const float* g0 = gsw + gg * 1024;
        float s = 0.f;
#pragma unroll 8
        for (int d = 0; d < 256; d++)
            s += g0[d] * Wgs[d * 64 + j];
        graph_out[(blockIdx.x * 4 + gg) * HG + j] = s * (1.0f / 64.0f) + __ldg(bg + j);
    }
}

// ---------------------------------------------------------------------------
extern "C" void kernel_launch(void* const* d_in, const int* in_sizes, int n_in,
                              void* d_out, int out_size) {
    const float* X  = (const float*)d_in[0];
    // d_in[1] = batch (int32): 64 consecutive nodes per graph, implicit
    const float* Wg = (const float*)d_in[2];
    const float* bg = (const float*)d_in[3];
    const float* Wn = (const float*)d_in[4];
    float* out = (float*)d_out;
    (void)in_sizes; (void)n_in; (void)out_size;

    cudaFuncSetAttribute(k_fused, cudaFuncAttributeMaxDynamicSharedMemorySize, SMEM_BYTES);

    // output layout: graph_out [2048*64] first, then node_out [131072*32]
    k_fused<<<512, 256, SMEM_BYTES>>>(X, Wn, Wg, bg, out, out + NUM_GRAPHS * HG);
}